// round 3
// baseline (speedup 1.0000x reference)
#include <cuda_runtime.h>

// ---------------------------------------------------------------------------
// CumulantSOAP: single-pass raw moments S1..S5 per column of X (N x P),
// fp64 partial reduction -> central moments -> cumulants -> (cum - mu) @ W.
// ---------------------------------------------------------------------------

#define NM   5
#define GMAX 320
#define PMAX 1024

// Scratch (no cudaMalloc allowed): partial raw-moment sums [m][block][col]
__device__ float g_partial[NM * GMAX * PMAX];
// (cumulants - mu), interleaved col*5 + q
__device__ float g_cum[NM * PMAX];

// ---- packed f32x2 helpers (Blackwell FFMA2 path, PTX-only) ----------------
static __device__ __forceinline__ unsigned long long f2_mul(unsigned long long a,
                                                            unsigned long long b) {
    unsigned long long d;
    asm("mul.rn.f32x2 %0, %1, %2;" : "=l"(d) : "l"(a), "l"(b));
    return d;
}
static __device__ __forceinline__ unsigned long long f2_add(unsigned long long a,
                                                            unsigned long long b) {
    unsigned long long d;
    asm("add.rn.f32x2 %0, %1, %2;" : "=l"(d) : "l"(a), "l"(b));
    return d;
}
static __device__ __forceinline__ unsigned long long f2_fma(unsigned long long a,
                                                            unsigned long long b,
                                                            unsigned long long c) {
    unsigned long long d;
    asm("fma.rn.f32x2 %0, %1, %2, %3;" : "=l"(d) : "l"(a), "l"(b), "l"(c));
    return d;
}
static __device__ __forceinline__ float2 f2_unpack(unsigned long long v) {
    float2 f;
    asm("mov.b64 {%0, %1}, %2;" : "=f"(f.x), "=f"(f.y) : "l"(v));
    return f;
}

// Accumulate one packed pair (2 elements) into 5 packed moment accumulators.
// 7 packed fma-pipe ops per 2 elements.
#define ACC(u, s1, s2, s3, s4, s5)                         \
    do {                                                   \
        unsigned long long _x2 = f2_mul((u), (u));         \
        unsigned long long _x3 = f2_mul(_x2, (u));         \
        (s1) = f2_add((s1), (u));                          \
        (s2) = f2_fma((u), (u), (s2));                     \
        (s3) = f2_fma(_x2, (u), (s3));                     \
        (s4) = f2_fma(_x2, _x2, (s4));                     \
        (s5) = f2_fma(_x3, _x2, (s5));                     \
    } while (0)

// ---------------------------------------------------------------------------
// Kernel 1: streaming raw moments. Block b handles rows b, b+G, b+2G, ...
// Thread t handles 4 consecutive columns (one LDG.128 per row).
// ---------------------------------------------------------------------------
__global__ __launch_bounds__(256, 2)
void k_moments(const float* __restrict__ X, int N, int P, int G) {
    const int b = blockIdx.x;
    const int tid = threadIdx.x;
    const int col4 = tid * 4;

    // packed accumulators: pair A = cols {c, c+1}, pair B = cols {c+2, c+3}
    unsigned long long s1a = 0ULL, s2a = 0ULL, s3a = 0ULL, s4a = 0ULL, s5a = 0ULL;
    unsigned long long s1b = 0ULL, s2b = 0ULL, s3b = 0ULL, s4b = 0ULL, s5b = 0ULL;

    const char* base = (const char*)(X + col4);
    const size_t rowBytes = (size_t)P * sizeof(float);

    int r = b;
    const int G4 = 4 * G;
    for (; r + 3 * G < N; r += G4) {
        ulonglong2 v0 = *(const ulonglong2*)(base + (size_t)r * rowBytes);
        ulonglong2 v1 = *(const ulonglong2*)(base + (size_t)(r + G) * rowBytes);
        ulonglong2 v2 = *(const ulonglong2*)(base + (size_t)(r + 2 * G) * rowBytes);
        ulonglong2 v3 = *(const ulonglong2*)(base + (size_t)(r + 3 * G) * rowBytes);
        ACC(v0.x, s1a, s2a, s3a, s4a, s5a);
        ACC(v0.y, s1b, s2b, s3b, s4b, s5b);
        ACC(v1.x, s1a, s2a, s3a, s4a, s5a);
        ACC(v1.y, s1b, s2b, s3b, s4b, s5b);
        ACC(v2.x, s1a, s2a, s3a, s4a, s5a);
        ACC(v2.y, s1b, s2b, s3b, s4b, s5b);
        ACC(v3.x, s1a, s2a, s3a, s4a, s5a);
        ACC(v3.y, s1b, s2b, s3b, s4b, s5b);
    }
    for (; r < N; r += G) {
        ulonglong2 v = *(const ulonglong2*)(base + (size_t)r * rowBytes);
        ACC(v.x, s1a, s2a, s3a, s4a, s5a);
        ACC(v.y, s1b, s2b, s3b, s4b, s5b);
    }

    // write partial sums: layout [m][b][col], coalesced float4 stores
    const size_t GP = (size_t)G * P;
    float* out = g_partial + (size_t)b * P + col4;
    float2 a, bb;
    a = f2_unpack(s1a); bb = f2_unpack(s1b);
    *(float4*)(out + 0 * GP) = make_float4(a.x, a.y, bb.x, bb.y);
    a = f2_unpack(s2a); bb = f2_unpack(s2b);
    *(float4*)(out + 1 * GP) = make_float4(a.x, a.y, bb.x, bb.y);
    a = f2_unpack(s3a); bb = f2_unpack(s3b);
    *(float4*)(out + 2 * GP) = make_float4(a.x, a.y, bb.x, bb.y);
    a = f2_unpack(s4a); bb = f2_unpack(s4b);
    *(float4*)(out + 3 * GP) = make_float4(a.x, a.y, bb.x, bb.y);
    a = f2_unpack(s5a); bb = f2_unpack(s5b);
    *(float4*)(out + 4 * GP) = make_float4(a.x, a.y, bb.x, bb.y);
}

// ---------------------------------------------------------------------------
// Kernel 2: reduce partials (fp64), raw -> central moments -> cumulants,
// subtract mu. Block = 32 columns x 8 slice-groups.
// ---------------------------------------------------------------------------
__global__ void k_reduce(const float* __restrict__ mu, int N, int P, int G) {
    const int cl = threadIdx.x & 31;
    const int s  = threadIdx.x >> 5;      // 0..7
    const int col = blockIdx.x * 32 + cl;
    const size_t GP = (size_t)G * P;

    double acc[NM] = {0.0, 0.0, 0.0, 0.0, 0.0};
    for (int b = s; b < G; b += 8) {
        const size_t off = (size_t)b * P + col;
#pragma unroll
        for (int m = 0; m < NM; m++)
            acc[m] += (double)g_partial[(size_t)m * GP + off];
    }

    __shared__ double smem[NM][8][32];
#pragma unroll
    for (int m = 0; m < NM; m++) smem[m][s][cl] = acc[m];
    __syncthreads();

    if (s == 0) {
        double t[NM];
#pragma unroll
        for (int m = 0; m < NM; m++) {
            double v = 0.0;
#pragma unroll
            for (int j = 0; j < 8; j++) v += smem[m][j][cl];
            t[m] = v;
        }
        const double invN = 1.0 / (double)N;
        const double m1 = t[0] * invN;
        const double r2 = t[1] * invN;
        const double r3 = t[2] * invN;
        const double r4 = t[3] * invN;
        const double r5 = t[4] * invN;
        const double m2 = m1 * m1;
        const double m3 = m2 * m1;

        const double mu2 = r2 - m2;
        const double mu3 = r3 - 3.0 * m1 * r2 + 2.0 * m3;
        const double mu4 = r4 - 4.0 * m1 * r3 + 6.0 * m2 * r2 - 3.0 * m2 * m2;
        const double mu5 = r5 - 5.0 * m1 * r4 + 10.0 * m2 * r3 - 10.0 * m3 * r2
                           + 4.0 * m3 * m2;

        const double c0 = m1;
        const double c1 = 0.0;                       // mean(centered) == 0
        const double c2 = mu2;
        const double c3 = mu3 - 3.0 * mu2 * mu2;
        const double c4 = mu5 - 10.0 * mu2 * mu3;

        const int j = col * NM;
        g_cum[j + 0] = (float)c0 - mu[j + 0];
        g_cum[j + 1] = (float)c1 - mu[j + 1];
        g_cum[j + 2] = (float)c2 - mu[j + 2];
        g_cum[j + 3] = (float)c3 - mu[j + 3];
        g_cum[j + 4] = (float)c4 - mu[j + 4];
    }
}

// ---------------------------------------------------------------------------
// Kernel 3: projection (cum - mu) @ W  -> K outputs. One warp per output.
// ---------------------------------------------------------------------------
__global__ void k_project(const float* __restrict__ W, float* __restrict__ out,
                          int P5, int K) {
    const int w = threadIdx.x >> 5;
    const int lane = threadIdx.x & 31;
    if (w >= K) return;
    double acc = 0.0;
    for (int i = lane; i < P5; i += 32)
        acc += (double)g_cum[i] * (double)W[(size_t)i * K + w];
#pragma unroll
    for (int o = 16; o > 0; o >>= 1)
        acc += __shfl_down_sync(0xffffffffu, acc, o);
    if (lane == 0) out[w] = (float)acc;
}

// ---------------------------------------------------------------------------
extern "C" void kernel_launch(void* const* d_in, const int* in_sizes, int n_in,
                              void* d_out, int out_size) {
    const float* X  = (const float*)d_in[0];
    const float* mu = (const float*)d_in[1];
    const float* W  = (const float*)d_in[2];
    float* out = (float*)d_out;

    const int P5 = in_sizes[1];          // P * 5
    const int P  = P5 / NM;              // 1024
    const int N  = in_sizes[0] / P;      // 100000
    const int K  = in_sizes[2] / P5;     // 8

    const int G = 296;                    // 2 blocks/SM, single wave

    k_moments<<<G, P / 4>>>(X, N, P, G);
    k_reduce<<<P / 32, 256>>>(mu, N, P, G);
    k_project<<<1, K * 32>>>(W, out, P5, K);
}

// round 4
// speedup vs baseline: 1.9359x; 1.9359x over previous
#include <cuda_runtime.h>

// ---------------------------------------------------------------------------
// CumulantSOAP: single-pass raw moments S1..S5 per column of X (N x P),
// fp32 partial reduction -> central moments (fp64, tiny) -> cumulants ->
// (cum - mu) @ W.
// ---------------------------------------------------------------------------

#define NM   5
#define GMAX 592
#define PMAX 1024

// Scratch (no cudaMalloc allowed): partial raw-moment sums [m][block][col]
__device__ float g_partial[NM * GMAX * PMAX];
// (cumulants - mu), interleaved col*5 + q
__device__ float g_cum[NM * PMAX];

// ---- packed f32x2 helpers (Blackwell FFMA2 path, PTX-only) ----------------
static __device__ __forceinline__ unsigned long long f2_mul(unsigned long long a,
                                                            unsigned long long b) {
    unsigned long long d;
    asm("mul.rn.f32x2 %0, %1, %2;" : "=l"(d) : "l"(a), "l"(b));
    return d;
}
static __device__ __forceinline__ unsigned long long f2_add(unsigned long long a,
                                                            unsigned long long b) {
    unsigned long long d;
    asm("add.rn.f32x2 %0, %1, %2;" : "=l"(d) : "l"(a), "l"(b));
    return d;
}
static __device__ __forceinline__ unsigned long long f2_fma(unsigned long long a,
                                                            unsigned long long b,
                                                            unsigned long long c) {
    unsigned long long d;
    asm("fma.rn.f32x2 %0, %1, %2, %3;" : "=l"(d) : "l"(a), "l"(b), "l"(c));
    return d;
}
static __device__ __forceinline__ float2 f2_unpack(unsigned long long v) {
    float2 f;
    asm("mov.b64 {%0, %1}, %2;" : "=f"(f.x), "=f"(f.y) : "l"(v));
    return f;
}

// Accumulate one packed pair (2 elements) into 5 packed moment accumulators.
// 7 packed fma-pipe ops per 2 elements.
#define ACC(u, s1, s2, s3, s4, s5)                         \
    do {                                                   \
        unsigned long long _x2 = f2_mul((u), (u));         \
        unsigned long long _x3 = f2_mul(_x2, (u));         \
        (s1) = f2_add((s1), (u));                          \
        (s2) = f2_fma((u), (u), (s2));                     \
        (s3) = f2_fma(_x2, (u), (s3));                     \
        (s4) = f2_fma(_x2, _x2, (s4));                     \
        (s5) = f2_fma(_x3, _x2, (s5));                     \
    } while (0)

// ---------------------------------------------------------------------------
// Kernel 1: streaming raw moments. Block b handles rows b, b+G, b+2G, ...
// Thread t handles 4 consecutive columns (one LDG.128 per row).
// 4 blocks/SM for deep memory-level parallelism.
// ---------------------------------------------------------------------------
__global__ __launch_bounds__(256, 4)
void k_moments(const float* __restrict__ X, int N, int P, int G) {
    const int b = blockIdx.x;
    const int tid = threadIdx.x;
    const int col4 = tid * 4;

    // packed accumulators: pair A = cols {c, c+1}, pair B = cols {c+2, c+3}
    unsigned long long s1a = 0ULL, s2a = 0ULL, s3a = 0ULL, s4a = 0ULL, s5a = 0ULL;
    unsigned long long s1b = 0ULL, s2b = 0ULL, s3b = 0ULL, s4b = 0ULL, s5b = 0ULL;

    const char* base = (const char*)(X + col4);
    const size_t rowBytes = (size_t)P * sizeof(float);

    int r = b;
    const int G4 = 4 * G;
    for (; r + 3 * G < N; r += G4) {
        ulonglong2 v0 = *(const ulonglong2*)(base + (size_t)r * rowBytes);
        ulonglong2 v1 = *(const ulonglong2*)(base + (size_t)(r + G) * rowBytes);
        ulonglong2 v2 = *(const ulonglong2*)(base + (size_t)(r + 2 * G) * rowBytes);
        ulonglong2 v3 = *(const ulonglong2*)(base + (size_t)(r + 3 * G) * rowBytes);
        ACC(v0.x, s1a, s2a, s3a, s4a, s5a);
        ACC(v0.y, s1b, s2b, s3b, s4b, s5b);
        ACC(v1.x, s1a, s2a, s3a, s4a, s5a);
        ACC(v1.y, s1b, s2b, s3b, s4b, s5b);
        ACC(v2.x, s1a, s2a, s3a, s4a, s5a);
        ACC(v2.y, s1b, s2b, s3b, s4b, s5b);
        ACC(v3.x, s1a, s2a, s3a, s4a, s5a);
        ACC(v3.y, s1b, s2b, s3b, s4b, s5b);
    }
    for (; r < N; r += G) {
        ulonglong2 v = *(const ulonglong2*)(base + (size_t)r * rowBytes);
        ACC(v.x, s1a, s2a, s3a, s4a, s5a);
        ACC(v.y, s1b, s2b, s3b, s4b, s5b);
    }

    // write partial sums: layout [m][b][col], coalesced float4 stores
    const size_t GP = (size_t)G * P;
    float* out = g_partial + (size_t)b * P + col4;
    float2 a, bb;
    a = f2_unpack(s1a); bb = f2_unpack(s1b);
    *(float4*)(out + 0 * GP) = make_float4(a.x, a.y, bb.x, bb.y);
    a = f2_unpack(s2a); bb = f2_unpack(s2b);
    *(float4*)(out + 1 * GP) = make_float4(a.x, a.y, bb.x, bb.y);
    a = f2_unpack(s3a); bb = f2_unpack(s3b);
    *(float4*)(out + 2 * GP) = make_float4(a.x, a.y, bb.x, bb.y);
    a = f2_unpack(s4a); bb = f2_unpack(s4b);
    *(float4*)(out + 3 * GP) = make_float4(a.x, a.y, bb.x, bb.y);
    a = f2_unpack(s5a); bb = f2_unpack(s5b);
    *(float4*)(out + 4 * GP) = make_float4(a.x, a.y, bb.x, bb.y);
}

// ---------------------------------------------------------------------------
// Kernel 2: reduce partials in FP32 (32-way split per column), then compute
// cumulants in fp64 (1024 columns only — negligible fp64 work).
// Block = 32 columns x 32 slice-groups (1024 threads).
// ---------------------------------------------------------------------------
__global__ __launch_bounds__(1024)
void k_reduce(const float* __restrict__ mu, int N, int P, int G) {
    const int cl = threadIdx.x & 31;      // column within the 32-col group
    const int s  = threadIdx.x >> 5;      // slice 0..31
    const int col = blockIdx.x * 32 + cl;
    const size_t GP = (size_t)G * P;

    float acc[NM] = {0.f, 0.f, 0.f, 0.f, 0.f};
    for (int b = s; b < G; b += 32) {
        const size_t off = (size_t)b * P + col;
#pragma unroll
        for (int m = 0; m < NM; m++)
            acc[m] += g_partial[(size_t)m * GP + off];
    }

    __shared__ float smem[NM][32][32];
#pragma unroll
    for (int m = 0; m < NM; m++) smem[m][s][cl] = acc[m];
    __syncthreads();

    if (s == 0) {
        double t[NM];
#pragma unroll
        for (int m = 0; m < NM; m++) {
            float v = 0.f;
#pragma unroll
            for (int j = 0; j < 32; j++) v += smem[m][j][cl];
            t[m] = (double)v;
        }
        const double invN = 1.0 / (double)N;
        const double m1 = t[0] * invN;
        const double r2 = t[1] * invN;
        const double r3 = t[2] * invN;
        const double r4 = t[3] * invN;
        const double r5 = t[4] * invN;
        const double m2 = m1 * m1;
        const double m3 = m2 * m1;

        const double mu2 = r2 - m2;
        const double mu3 = r3 - 3.0 * m1 * r2 + 2.0 * m3;
        const double mu5 = r5 - 5.0 * m1 * r4 + 10.0 * m2 * r3 - 10.0 * m3 * r2
                           + 4.0 * m3 * m2;

        const double c0 = m1;
        const double c1 = 0.0;                       // mean(centered) == 0
        const double c2 = mu2;
        const double c3 = mu3 - 3.0 * mu2 * mu2;
        const double c4 = mu5 - 10.0 * mu2 * mu3;

        const int j = col * NM;
        g_cum[j + 0] = (float)c0 - mu[j + 0];
        g_cum[j + 1] = (float)c1 - mu[j + 1];
        g_cum[j + 2] = (float)c2 - mu[j + 2];
        g_cum[j + 3] = (float)c3 - mu[j + 3];
        g_cum[j + 4] = (float)c4 - mu[j + 4];
    }
}

// ---------------------------------------------------------------------------
// Kernel 3: projection (cum - mu) @ W -> K outputs (K == 8 fast path).
// Single block, 1024 threads, fp32, float4 W loads.
// ---------------------------------------------------------------------------
__global__ __launch_bounds__(1024)
void k_project8(const float* __restrict__ W, float* __restrict__ out, int P5) {
    const int tid = threadIdx.x;
    float a0 = 0.f, a1 = 0.f, a2 = 0.f, a3 = 0.f;
    float a4 = 0.f, a5 = 0.f, a6 = 0.f, a7 = 0.f;

    for (int i = tid; i < P5; i += 1024) {
        const float c = g_cum[i];
        const float4 w0 = *(const float4*)(W + (size_t)i * 8);
        const float4 w1 = *(const float4*)(W + (size_t)i * 8 + 4);
        a0 += c * w0.x; a1 += c * w0.y; a2 += c * w0.z; a3 += c * w0.w;
        a4 += c * w1.x; a5 += c * w1.y; a6 += c * w1.z; a7 += c * w1.w;
    }

    // warp reduce each accumulator
#pragma unroll
    for (int o = 16; o > 0; o >>= 1) {
        a0 += __shfl_down_sync(0xffffffffu, a0, o);
        a1 += __shfl_down_sync(0xffffffffu, a1, o);
        a2 += __shfl_down_sync(0xffffffffu, a2, o);
        a3 += __shfl_down_sync(0xffffffffu, a3, o);
        a4 += __shfl_down_sync(0xffffffffu, a4, o);
        a5 += __shfl_down_sync(0xffffffffu, a5, o);
        a6 += __shfl_down_sync(0xffffffffu, a6, o);
        a7 += __shfl_down_sync(0xffffffffu, a7, o);
    }

    __shared__ float sred[32][8];
    const int w = tid >> 5;
    if ((tid & 31) == 0) {
        sred[w][0] = a0; sred[w][1] = a1; sred[w][2] = a2; sred[w][3] = a3;
        sred[w][4] = a4; sred[w][5] = a5; sred[w][6] = a6; sred[w][7] = a7;
    }
    __syncthreads();
    if (tid < 8) {
        float v = 0.f;
#pragma unroll
        for (int j = 0; j < 32; j++) v += sred[j][tid];
        out[tid] = v;
    }
}

// Generic fallback (K != 8): one warp per output, fp32.
__global__ void k_project_gen(const float* __restrict__ W, float* __restrict__ out,
                              int P5, int K) {
    const int w = blockIdx.x;
    const int lane = threadIdx.x;
    float acc = 0.f;
    for (int i = lane; i < P5; i += 32)
        acc += g_cum[i] * W[(size_t)i * K + w];
#pragma unroll
    for (int o = 16; o > 0; o >>= 1)
        acc += __shfl_down_sync(0xffffffffu, acc, o);
    if (lane == 0) out[w] = acc;
}

// ---------------------------------------------------------------------------
extern "C" void kernel_launch(void* const* d_in, const int* in_sizes, int n_in,
                              void* d_out, int out_size) {
    const float* X  = (const float*)d_in[0];
    const float* mu = (const float*)d_in[1];
    const float* W  = (const float*)d_in[2];
    float* out = (float*)d_out;

    const int P5 = in_sizes[1];          // P * 5
    const int P  = P5 / NM;              // 1024
    const int N  = in_sizes[0] / P;      // 100000
    const int K  = in_sizes[2] / P5;     // 8

    const int G = 592;                    // 4 blocks/SM, single wave

    k_moments<<<G, P / 4>>>(X, N, P, G);
    k_reduce<<<P / 32, 1024>>>(mu, N, P, G);
    if (K == 8)
        k_project8<<<1, 1024>>>(W, out, P5);
    else
        k_project_gen<<<K, 32>>>(W, out, P5, K);
}

// round 5
// speedup vs baseline: 1.9545x; 1.0096x over previous
#include <cuda_runtime.h>

// ---------------------------------------------------------------------------
// CumulantSOAP: single-pass raw moments S1..S5 per column of X (N x P),
// 2-stage fp32 partial reduction -> central moments (fp64, tiny) ->
// cumulants -> (cum - mu) @ W.
// ---------------------------------------------------------------------------

#define NM    5
#define GMAX  592
#define PMAX  1024
#define NSLC  8          // stage-A slice count

// Scratch (no cudaMalloc allowed)
__device__ float g_partial[NM * GMAX * PMAX];    // [m][block][col]
__device__ float g_partial2[NM * NSLC * PMAX];   // [m][slice][col]
__device__ float g_cum[NM * PMAX];               // (cumulants - mu), col*5+q

// ---- packed f32x2 helpers (Blackwell FFMA2 path, PTX-only) ----------------
static __device__ __forceinline__ unsigned long long f2_mul(unsigned long long a,
                                                            unsigned long long b) {
    unsigned long long d;
    asm("mul.rn.f32x2 %0, %1, %2;" : "=l"(d) : "l"(a), "l"(b));
    return d;
}
static __device__ __forceinline__ unsigned long long f2_add(unsigned long long a,
                                                            unsigned long long b) {
    unsigned long long d;
    asm("add.rn.f32x2 %0, %1, %2;" : "=l"(d) : "l"(a), "l"(b));
    return d;
}
static __device__ __forceinline__ unsigned long long f2_fma(unsigned long long a,
                                                            unsigned long long b,
                                                            unsigned long long c) {
    unsigned long long d;
    asm("fma.rn.f32x2 %0, %1, %2, %3;" : "=l"(d) : "l"(a), "l"(b), "l"(c));
    return d;
}
static __device__ __forceinline__ float2 f2_unpack(unsigned long long v) {
    float2 f;
    asm("mov.b64 {%0, %1}, %2;" : "=f"(f.x), "=f"(f.y) : "l"(v));
    return f;
}

// Accumulate one packed pair (2 elements) into 5 packed moment accumulators.
#define ACC(u, s1, s2, s3, s4, s5)                         \
    do {                                                   \
        unsigned long long _x2 = f2_mul((u), (u));         \
        unsigned long long _x3 = f2_mul(_x2, (u));         \
        (s1) = f2_add((s1), (u));                          \
        (s2) = f2_fma((u), (u), (s2));                     \
        (s3) = f2_fma(_x2, (u), (s3));                     \
        (s4) = f2_fma(_x2, _x2, (s4));                     \
        (s5) = f2_fma(_x3, _x2, (s5));                     \
    } while (0)

// ---------------------------------------------------------------------------
// Kernel 1: streaming raw moments. Block b handles rows b, b+G, b+2G, ...
// Thread t handles 4 consecutive columns (one LDG.128 per row).
// ---------------------------------------------------------------------------
__global__ __launch_bounds__(256, 4)
void k_moments(const float* __restrict__ X, int N, int P, int G) {
    const int b = blockIdx.x;
    const int tid = threadIdx.x;
    const int col4 = tid * 4;

    unsigned long long s1a = 0ULL, s2a = 0ULL, s3a = 0ULL, s4a = 0ULL, s5a = 0ULL;
    unsigned long long s1b = 0ULL, s2b = 0ULL, s3b = 0ULL, s4b = 0ULL, s5b = 0ULL;

    const char* base = (const char*)(X + col4);
    const size_t rowBytes = (size_t)P * sizeof(float);

    int r = b;
    const int G4 = 4 * G;
    for (; r + 3 * G < N; r += G4) {
        ulonglong2 v0 = *(const ulonglong2*)(base + (size_t)r * rowBytes);
        ulonglong2 v1 = *(const ulonglong2*)(base + (size_t)(r + G) * rowBytes);
        ulonglong2 v2 = *(const ulonglong2*)(base + (size_t)(r + 2 * G) * rowBytes);
        ulonglong2 v3 = *(const ulonglong2*)(base + (size_t)(r + 3 * G) * rowBytes);
        ACC(v0.x, s1a, s2a, s3a, s4a, s5a);
        ACC(v0.y, s1b, s2b, s3b, s4b, s5b);
        ACC(v1.x, s1a, s2a, s3a, s4a, s5a);
        ACC(v1.y, s1b, s2b, s3b, s4b, s5b);
        ACC(v2.x, s1a, s2a, s3a, s4a, s5a);
        ACC(v2.y, s1b, s2b, s3b, s4b, s5b);
        ACC(v3.x, s1a, s2a, s3a, s4a, s5a);
        ACC(v3.y, s1b, s2b, s3b, s4b, s5b);
    }
    for (; r < N; r += G) {
        ulonglong2 v = *(const ulonglong2*)(base + (size_t)r * rowBytes);
        ACC(v.x, s1a, s2a, s3a, s4a, s5a);
        ACC(v.y, s1b, s2b, s3b, s4b, s5b);
    }

    const size_t GP = (size_t)G * P;
    float* out = g_partial + (size_t)b * P + col4;
    float2 a, bb;
    a = f2_unpack(s1a); bb = f2_unpack(s1b);
    *(float4*)(out + 0 * GP) = make_float4(a.x, a.y, bb.x, bb.y);
    a = f2_unpack(s2a); bb = f2_unpack(s2b);
    *(float4*)(out + 1 * GP) = make_float4(a.x, a.y, bb.x, bb.y);
    a = f2_unpack(s3a); bb = f2_unpack(s3b);
    *(float4*)(out + 2 * GP) = make_float4(a.x, a.y, bb.x, bb.y);
    a = f2_unpack(s4a); bb = f2_unpack(s4b);
    *(float4*)(out + 3 * GP) = make_float4(a.x, a.y, bb.x, bb.y);
    a = f2_unpack(s5a); bb = f2_unpack(s5b);
    *(float4*)(out + 4 * GP) = make_float4(a.x, a.y, bb.x, bb.y);
}

// ---------------------------------------------------------------------------
// Kernel 2a: stage-A reduction. grid = (P/32, NSLC). Block = 256 threads
// (32 cols x 8 subslices). Block (cg, gs) reduces its G/NSLC chunk of
// partials for 32 columns -> g_partial2[m][gs][col]. All L2-hit.
// ---------------------------------------------------------------------------
__global__ __launch_bounds__(256)
void k_reduceA(int P, int G) {
    const int cl = threadIdx.x & 31;
    const int ss = threadIdx.x >> 5;                 // 0..7
    const int col = blockIdx.x * 32 + cl;
    const int gs = blockIdx.y;                       // 0..NSLC-1
    const int chunk = G / NSLC;                      // 74
    const int b0 = gs * chunk;
    const int b1 = (gs == NSLC - 1) ? G : b0 + chunk;
    const size_t GP = (size_t)G * P;

    float acc[NM] = {0.f, 0.f, 0.f, 0.f, 0.f};
    for (int b = b0 + ss; b < b1; b += 8) {
        const size_t off = (size_t)b * P + col;
#pragma unroll
        for (int m = 0; m < NM; m++)
            acc[m] += g_partial[(size_t)m * GP + off];
    }

    __shared__ float smem[NM][8][32];
#pragma unroll
    for (int m = 0; m < NM; m++) smem[m][ss][cl] = acc[m];
    __syncthreads();

    if (ss == 0) {
#pragma unroll
        for (int m = 0; m < NM; m++) {
            float v = 0.f;
#pragma unroll
            for (int j = 0; j < 8; j++) v += smem[m][j][cl];
            g_partial2[(size_t)m * (NSLC * PMAX) + (size_t)gs * PMAX + col] = v;
        }
    }
}

// ---------------------------------------------------------------------------
// Kernel 2b: stage-B fold (8 values/col/moment) + fp64 cumulant algebra +
// mu subtraction. grid = P/128, 128 threads, one column per thread.
// ---------------------------------------------------------------------------
__global__ __launch_bounds__(128)
void k_reduceB(const float* __restrict__ mu, int N, int P) {
    const int col = blockIdx.x * 128 + threadIdx.x;
    if (col >= P) return;

    double t[NM];
#pragma unroll
    for (int m = 0; m < NM; m++) {
        float v = 0.f;
#pragma unroll
        for (int j = 0; j < NSLC; j++)
            v += g_partial2[(size_t)m * (NSLC * PMAX) + (size_t)j * PMAX + col];
        t[m] = (double)v;
    }

    const double invN = 1.0 / (double)N;
    const double m1 = t[0] * invN;
    const double r2 = t[1] * invN;
    const double r3 = t[2] * invN;
    const double r4 = t[3] * invN;
    const double r5 = t[4] * invN;
    const double m2 = m1 * m1;
    const double m3 = m2 * m1;

    const double mu2 = r2 - m2;
    const double mu3 = r3 - 3.0 * m1 * r2 + 2.0 * m3;
    const double mu5 = r5 - 5.0 * m1 * r4 + 10.0 * m2 * r3 - 10.0 * m3 * r2
                       + 4.0 * m3 * m2;

    const double c0 = m1;
    const double c1 = 0.0;                           // mean(centered) == 0
    const double c2 = mu2;
    const double c3 = mu3 - 3.0 * mu2 * mu2;
    const double c4 = mu5 - 10.0 * mu2 * mu3;

    const int j = col * NM;
    g_cum[j + 0] = (float)c0 - mu[j + 0];
    g_cum[j + 1] = (float)c1 - mu[j + 1];
    g_cum[j + 2] = (float)c2 - mu[j + 2];
    g_cum[j + 3] = (float)c3 - mu[j + 3];
    g_cum[j + 4] = (float)c4 - mu[j + 4];
}

// ---------------------------------------------------------------------------
// Kernel 3: projection (cum - mu) @ W -> 8 outputs. Single 1024-thread block.
// ---------------------------------------------------------------------------
__global__ __launch_bounds__(1024)
void k_project8(const float* __restrict__ W, float* __restrict__ out, int P5) {
    const int tid = threadIdx.x;
    float a0 = 0.f, a1 = 0.f, a2 = 0.f, a3 = 0.f;
    float a4 = 0.f, a5 = 0.f, a6 = 0.f, a7 = 0.f;

    for (int i = tid; i < P5; i += 1024) {
        const float c = g_cum[i];
        const float4 w0 = *(const float4*)(W + (size_t)i * 8);
        const float4 w1 = *(const float4*)(W + (size_t)i * 8 + 4);
        a0 += c * w0.x; a1 += c * w0.y; a2 += c * w0.z; a3 += c * w0.w;
        a4 += c * w1.x; a5 += c * w1.y; a6 += c * w1.z; a7 += c * w1.w;
    }

#pragma unroll
    for (int o = 16; o > 0; o >>= 1) {
        a0 += __shfl_down_sync(0xffffffffu, a0, o);
        a1 += __shfl_down_sync(0xffffffffu, a1, o);
        a2 += __shfl_down_sync(0xffffffffu, a2, o);
        a3 += __shfl_down_sync(0xffffffffu, a3, o);
        a4 += __shfl_down_sync(0xffffffffu, a4, o);
        a5 += __shfl_down_sync(0xffffffffu, a5, o);
        a6 += __shfl_down_sync(0xffffffffu, a6, o);
        a7 += __shfl_down_sync(0xffffffffu, a7, o);
    }

    __shared__ float sred[32][8];
    const int w = tid >> 5;
    if ((tid & 31) == 0) {
        sred[w][0] = a0; sred[w][1] = a1; sred[w][2] = a2; sred[w][3] = a3;
        sred[w][4] = a4; sred[w][5] = a5; sred[w][6] = a6; sred[w][7] = a7;
    }
    __syncthreads();
    if (tid < 8) {
        float v = 0.f;
#pragma unroll
        for (int j = 0; j < 32; j++) v += sred[j][tid];
        out[tid] = v;
    }
}

// Generic fallback (K != 8): one warp per output, fp32.
__global__ void k_project_gen(const float* __restrict__ W, float* __restrict__ out,
                              int P5, int K) {
    const int w = blockIdx.x;
    const int lane = threadIdx.x;
    float acc = 0.f;
    for (int i = lane; i < P5; i += 32)
        acc += g_cum[i] * W[(size_t)i * K + w];
#pragma unroll
    for (int o = 16; o > 0; o >>= 1)
        acc += __shfl_down_sync(0xffffffffu, acc, o);
    if (lane == 0) out[w] = acc;
}

// ---------------------------------------------------------------------------
extern "C" void kernel_launch(void* const* d_in, const int* in_sizes, int n_in,
                              void* d_out, int out_size) {
    const float* X  = (const float*)d_in[0];
    const float* mu = (const float*)d_in[1];
    const float* W  = (const float*)d_in[2];
    float* out = (float*)d_out;

    const int P5 = in_sizes[1];          // P * 5
    const int P  = P5 / NM;              // 1024
    const int N  = in_sizes[0] / P;      // 100000
    const int K  = in_sizes[2] / P5;     // 8

    const int G = 592;                    // 4 blocks/SM, single wave

    k_moments<<<G, P / 4>>>(X, N, P, G);
    dim3 gridA(P / 32, NSLC);
    k_reduceA<<<gridA, 256>>>(P, G);
    k_reduceB<<<(P + 127) / 128, 128>>>(mu, N, P);
    if (K == 8)
        k_project8<<<1, 1024>>>(W, out, P5);
    else
        k_project_gen<<<K, 32>>>(W, out, P5, K);
}